// round 9
// baseline (speedup 1.0000x reference)
#include <cuda_runtime.h>
#include <cuda_fp16.h>
#include <cstdint>

#define M_DIM    64
#define K_DIM    4096
#define N_DIM    11008
#define NGROUPS  32
#define KC       64                    // k per chunk
#define SPLIT    4                     // K-split factor
#define CPS      (K_DIM / KC / SPLIT)  // chunks per split = 16
#define NTILE    64                    // n columns per CTA
#define NTHREADS 128

// One-time fp16 image of x with k-permutation baked in:
// within each 8-k word, slot p holds original nibble index jmap[p],
// jmap = {0,4,1,5,2,6,3,7}  (matches the LOP3 pair extraction (j, j+4)).
__device__ __half g_xh[M_DIM * K_DIM];              // 512 KB
__device__ float  g_part[SPLIT][M_DIM * N_DIM];     // 11.3 MB split-K partials

__device__ __forceinline__ uint32_t smem_u32(const void* p) {
    uint32_t a;
    asm("{ .reg .u64 t; cvta.to.shared.u64 t, %1; cvt.u32.u64 %0, t; }" : "=r"(a) : "l"(p));
    return a;
}

// ---------------------------------------------------------------------------
// Kernel 1: x[M,K] fp32 -> g_xh fp16 with permuted k-order within 8-k words
// ---------------------------------------------------------------------------
__global__ __launch_bounds__(256) void prep_x_kernel(const float* __restrict__ x) {
    const int t = blockIdx.x * 256 + threadIdx.x;   // 32768 threads
    const int i = t & 511;                          // k-word (8 k each)
    const int m = t >> 9;                           // 0..63
    const float* src = x + m * K_DIM + 8 * i;
    __half2 h[4];
    h[0] = __floats2half2_rn(src[0], src[4]);
    h[1] = __floats2half2_rn(src[1], src[5]);
    h[2] = __floats2half2_rn(src[2], src[6]);
    h[3] = __floats2half2_rn(src[3], src[7]);
    *reinterpret_cast<uint4*>(g_xh + m * K_DIM + 8 * i) = *reinterpret_cast<const uint4*>(h);
}

// ---------------------------------------------------------------------------
// Kernel 2: fused int4-dequant GEMM via mma.sync m16n8k16 (fp16 in, fp32 acc)
// CTA: 64m x 64n x K/4, 4 warps (2m x 2n), warp tile 32m x 32n.
// Grid (172, 4): blockIdx.x = n-tile, blockIdx.y = k-split.
// SMEM swizzle: 16B group kg at row r lives at  r*128 + ((kg ^ (r&7))*16).
// ---------------------------------------------------------------------------
__device__ __forceinline__ void dequant_word(unsigned word, uint32_t zz, uint32_t s2,
                                             uint32_t sts) {
    uint32_t r[4];
#pragma unroll
    for (int j = 0; j < 4; j++) {
        uint32_t p;
        asm("lop3.b32 %0, %1, 0x000F000F, 0x64006400, 0xEA;" : "=r"(p) : "r"(word >> (4 * j)));
        asm("sub.rn.f16x2 %0, %0, %1;" : "+r"(p) : "r"(zz));
        asm("mul.rn.f16x2 %0, %1, %2;" : "=r"(r[j]) : "r"(p), "r"(s2));
    }
    asm volatile("st.shared.v4.b32 [%0], {%1,%2,%3,%4};"
        :: "r"(sts), "r"(r[0]), "r"(r[1]), "r"(r[2]), "r"(r[3]) : "memory");
}

__global__ __launch_bounds__(NTHREADS, 5)
void gptq_hmma_kernel(const int*   __restrict__ qweight,  // [K/8, N]
                      const int*   __restrict__ qzeros,   // [NGROUPS, N/8]
                      const float* __restrict__ scales)   // [NGROUPS, N]
{
    __shared__ __half a_s[2][M_DIM * KC];   // x tile   2 x 8 KB
    __shared__ __half w_s[2][NTILE * KC];   // W tile   2 x 8 KB

    const int tid   = threadIdx.x;
    const int lane  = tid & 31;
    const int wid   = tid >> 5;
    const int nblk  = blockIdx.x * NTILE;
    const int split = blockIdx.y;
    const int cbase = split * CPS;

    const uint32_t a_base = smem_u32(a_s);
    const uint32_t w_base = smem_u32(w_s);

    // ---- dequant assignment: 4 qweight words / thread / chunk (one column)
    const int dq_n  = tid & 63;             // local n
    const int kwh   = tid >> 6;             // 0/1 -> words 0-3 or 4-7
    const int dq_gn = nblk + dq_n;
    uint32_t dq_sts[4];
#pragma unroll
    for (int j = 0; j < 4; j++)
        dq_sts[j] = w_base + (uint32_t)(dq_n * 128 + (((kwh * 4 + j) ^ (dq_n & 7)) * 16));

    // ---- x stage assignment: four 16B groups / thread / chunk
    uint32_t xs_dst[4];
    const __half* xs_src[4];
#pragma unroll
    for (int i = 0; i < 4; i++) {
        const int v  = tid + i * NTHREADS;   // 0..511
        const int m  = v >> 3;
        const int kg = v & 7;
        xs_dst[i] = a_base + (uint32_t)(m * 128 + ((kg ^ (m & 7)) * 16));
        xs_src[i] = g_xh + m * K_DIM + cbase * KC + kg * 8;
    }

    // ---- compute assignment: warp (wm, wn), tile 32m x 32n
    const int wm = wid & 1, wn = wid >> 1;
    const int m0  = wm * 32;
    const int nw0 = wn * 32;
    const int lrow_a = m0  + (lane & 15);
    const int lrow_b = nw0 + (lane & 15);
    const int khalf  = lane >> 4;            // 0: k+0, 1: k+8
    const uint32_t ldm_a0 = a_base + (uint32_t)(lrow_a * 128);
    const uint32_t ldm_a1 = ldm_a0 + 16u * 128u;     // rows +16 (same swizzle phase)
    const uint32_t ldm_b0 = w_base + (uint32_t)(lrow_b * 128);
    const uint32_t ldm_b1 = ldm_b0 + 16u * 128u;
    const int swz_a = lrow_a & 7, swz_b = lrow_b & 7;

    float acc[2][2][2][4] = {};   // [mi][nj][n8][4]

    // ================= stage chunk 0 of this split =================
    {
#pragma unroll
        for (int i = 0; i < 4; i++)
            asm volatile("cp.async.ca.shared.global [%0], [%1], 16;"
                :: "r"(xs_dst[i]), "l"(xs_src[i]) : "memory");
        asm volatile("cp.async.commit_group;" ::: "memory");

        const int c0 = cbase;
        const int g  = c0 >> 1;
        unsigned w[4];
#pragma unroll
        for (int j = 0; j < 4; j++)
            w[j] = (unsigned)qweight[(c0 * 8 + kwh * 4 + j) * N_DIM + dq_gn];
        const float    s  = scales[g * N_DIM + dq_gn];
        const int      zw = qzeros[g * (N_DIM / 8) + (dq_gn >> 3)];
        const int      z  = ((zw >> ((dq_gn & 7) * 4)) & 15) + 1;
        const uint32_t zz = 0x64006400u + (uint32_t)z * 0x00010001u;
        const uint16_t hb = __half_as_ushort(__float2half_rn(s));
        const uint32_t s2 = ((uint32_t)hb << 16) | hb;
#pragma unroll
        for (int j = 0; j < 4; j++) dequant_word(w[j], zz, s2, dq_sts[j]);
        asm volatile("cp.async.wait_group 0;" ::: "memory");
    }
    __syncthreads();

    // ================= main loop =================
#pragma unroll 1
    for (int lc = 0; lc < CPS; lc++) {
        const uint32_t aoff  = (uint32_t)((lc & 1) * (M_DIM * KC * 2));
        const uint32_t woff  = (uint32_t)((lc & 1) * (NTILE * KC * 2));
        const uint32_t naoff = (uint32_t)(((lc + 1) & 1) * (M_DIM * KC * 2));
        const uint32_t nwoff = (uint32_t)(((lc + 1) & 1) * (NTILE * KC * 2));

        unsigned nwd[4]; uint32_t nzz = 0, ns2 = 0;
        const bool has_next = (lc + 1 < CPS);
        if (has_next) {
            const int nc = cbase + lc + 1;
#pragma unroll
            for (int i = 0; i < 4; i++)
                asm volatile("cp.async.ca.shared.global [%0], [%1], 16;"
                    :: "r"(xs_dst[i] + naoff), "l"(xs_src[i] + (lc + 1) * KC) : "memory");
            asm volatile("cp.async.commit_group;" ::: "memory");

            const int g = nc >> 1;
#pragma unroll
            for (int j = 0; j < 4; j++)
                nwd[j] = (unsigned)qweight[(nc * 8 + kwh * 4 + j) * N_DIM + dq_gn];
            const float s  = scales[g * N_DIM + dq_gn];
            const int   zw = qzeros[g * (N_DIM / 8) + (dq_gn >> 3)];
            const int   z  = ((zw >> ((dq_gn & 7) * 4)) & 15) + 1;
            nzz = 0x64006400u + (uint32_t)z * 0x00010001u;
            const uint16_t hb = __half_as_ushort(__float2half_rn(s));
            ns2 = ((uint32_t)hb << 16) | hb;
        }

        // ---- compute chunk: 4 k-tiles of 16; per kt: 4 LDSM, 8 MMA
#pragma unroll
        for (int kt = 0; kt < 4; kt++) {
            const int kg = 2 * kt + khalf;
            uint32_t a0[4], a1[4], b0[4], b1[4];
            asm volatile("ldmatrix.sync.aligned.m8n8.x4.shared.b16 {%0,%1,%2,%3}, [%4];"
                : "=r"(a0[0]), "=r"(a0[1]), "=r"(a0[2]), "=r"(a0[3])
                : "r"(ldm_a0 + aoff + (uint32_t)((kg ^ swz_a) * 16)));
            asm volatile("ldmatrix.sync.aligned.m8n8.x4.shared.b16 {%0,%1,%2,%3}, [%4];"
                : "=r"(a1[0]), "=r"(a1[1]), "=r"(a1[2]), "=r"(a1[3])
                : "r"(ldm_a1 + aoff + (uint32_t)((kg ^ swz_a) * 16)));
            asm volatile("ldmatrix.sync.aligned.m8n8.x4.shared.b16 {%0,%1,%2,%3}, [%4];"
                : "=r"(b0[0]), "=r"(b0[1]), "=r"(b0[2]), "=r"(b0[3])
                : "r"(ldm_b0 + woff + (uint32_t)((kg ^ swz_b) * 16)));
            asm volatile("ldmatrix.sync.aligned.m8n8.x4.shared.b16 {%0,%1,%2,%3}, [%4];"
                : "=r"(b1[0]), "=r"(b1[1]), "=r"(b1[2]), "=r"(b1[3])
                : "r"(ldm_b1 + woff + (uint32_t)((kg ^ swz_b) * 16)));
#pragma unroll
            for (int mi = 0; mi < 2; mi++) {
                const uint32_t* a = mi ? a1 : a0;
#pragma unroll
                for (int nj = 0; nj < 2; nj++) {
                    const uint32_t* b = nj ? b1 : b0;
                    asm volatile(
                        "mma.sync.aligned.m16n8k16.row.col.f32.f16.f16.f32 "
                        "{%0,%1,%2,%3}, {%4,%5,%6,%7}, {%8,%9}, {%0,%1,%2,%3};"
                        : "+f"(acc[mi][nj][0][0]), "+f"(acc[mi][nj][0][1]),
                          "+f"(acc[mi][nj][0][2]), "+f"(acc[mi][nj][0][3])
                        : "r"(a[0]), "r"(a[1]), "r"(a[2]), "r"(a[3]), "r"(b[0]), "r"(b[2]));
                    asm volatile(
                        "mma.sync.aligned.m16n8k16.row.col.f32.f16.f16.f32 "
                        "{%0,%1,%2,%3}, {%4,%5,%6,%7}, {%8,%9}, {%0,%1,%2,%3};"
                        : "+f"(acc[mi][nj][1][0]), "+f"(acc[mi][nj][1][1]),
                          "+f"(acc[mi][nj][1][2]), "+f"(acc[mi][nj][1][3])
                        : "r"(a[0]), "r"(a[1]), "r"(a[2]), "r"(a[3]), "r"(b[1]), "r"(b[3]));
                }
            }
        }

        if (has_next) {
            dequant_word(nwd[0], nzz, ns2, dq_sts[0] + nwoff);
            dequant_word(nwd[1], nzz, ns2, dq_sts[1] + nwoff);
            dequant_word(nwd[2], nzz, ns2, dq_sts[2] + nwoff);
            dequant_word(nwd[3], nzz, ns2, dq_sts[3] + nwoff);
            asm volatile("cp.async.wait_group 0;" ::: "memory");
        }
        __syncthreads();
    }

    // ================= epilogue: store partials (no bias) =================
    {
        float* part = g_part[split];
        const int r   = lane >> 2;
        const int c4  = (lane & 3) * 2;
#pragma unroll
        for (int mi = 0; mi < 2; mi++) {
#pragma unroll
            for (int nj = 0; nj < 2; nj++) {
#pragma unroll
                for (int t = 0; t < 2; t++) {
                    const int gn   = nblk + nw0 + nj * 16 + t * 8 + c4;
                    const int mrow = m0 + mi * 16 + r;
                    *reinterpret_cast<float2*>(part + (size_t)mrow * N_DIM + gn) =
                        make_float2(acc[mi][nj][t][0], acc[mi][nj][t][1]);
                    *reinterpret_cast<float2*>(part + (size_t)(mrow + 8) * N_DIM + gn) =
                        make_float2(acc[mi][nj][t][2], acc[mi][nj][t][3]);
                }
            }
        }
    }
}

// ---------------------------------------------------------------------------
// Kernel 3: reduce partials + bias -> out
// ---------------------------------------------------------------------------
__global__ __launch_bounds__(256) void reduce_kernel(const float* __restrict__ bias,
                                                     float* __restrict__ out) {
    const int t = blockIdx.x * 256 + threadIdx.x;    // 176128 threads
    const int m    = t / (N_DIM / 4);
    const int col4 = t % (N_DIM / 4);
    const size_t idx = (size_t)m * N_DIM + col4 * 4;
    float4 s = *reinterpret_cast<const float4*>(&g_part[0][idx]);
#pragma unroll
    for (int p = 1; p < SPLIT; p++) {
        const float4 v = *reinterpret_cast<const float4*>(&g_part[p][idx]);
        s.x += v.x; s.y += v.y; s.z += v.z; s.w += v.w;
    }
    const float4 b = *reinterpret_cast<const float4*>(bias + col4 * 4);
    s.x += b.x; s.y += b.y; s.z += b.z; s.w += b.w;
    *reinterpret_cast<float4*>(out + idx) = s;
}

// ---------------------------------------------------------------------------
extern "C" void kernel_launch(void* const* d_in, const int* in_sizes, int n_in,
                              void* d_out, int out_size) {
    const float* x       = (const float*)d_in[0];
    const int*   qweight = (const int*)  d_in[1];
    const int*   qzeros  = (const int*)  d_in[2];
    const float* scales  = (const float*)d_in[3];
    const float* bias    = (const float*)d_in[4];
    float*       out     = (float*)d_out;

    prep_x_kernel<<<128, 256>>>(x);
    gptq_hmma_kernel<<<dim3(N_DIM / NTILE, SPLIT), NTHREADS>>>(qweight, qzeros, scales);
    reduce_kernel<<<(M_DIM * N_DIM / 4) / 256, 256>>>(bias, out);
}

// round 13
// speedup vs baseline: 1.3960x; 1.3960x over previous
#include <cuda_runtime.h>
#include <cuda_fp16.h>
#include <cstdint>

#define M_DIM    64
#define K_DIM    4096
#define N_DIM    11008
#define NGROUPS  32
#define KC       64                    // k per chunk
#define SPLIT    8                     // K-split factor
#define CPS      (K_DIM / KC / SPLIT)  // chunks per split = 8
#define NTILE    64                    // n columns per CTA
#define NTB      (N_DIM / NTILE)       // 172 n-tiles
#define NTHREADS 128

// One-time fp16 image of x with k-permutation baked in:
// within each 8-k word, slot p holds original nibble index jmap[p],
// jmap = {0,4,1,5,2,6,3,7}  (matches the LOP3 pair extraction (j, j+4)).
__device__ __half  g_xh[M_DIM * K_DIM];                 // 512 KB
__device__ float4  g_part4[SPLIT * NTB * 1024];         // 22.5 MB flat split-K partials

__device__ __forceinline__ uint32_t smem_u32(const void* p) {
    uint32_t a;
    asm("{ .reg .u64 t; cvta.to.shared.u64 t, %1; cvt.u32.u64 %0, t; }" : "=r"(a) : "l"(p));
    return a;
}

// ---------------------------------------------------------------------------
// Kernel 1: x[M,K] fp32 -> g_xh fp16, permuted k-order. 4 words/thread, MLP=4.
// word w (0..32767): src = x + 8w, dst = g_xh + 8w.
// ---------------------------------------------------------------------------
__global__ __launch_bounds__(256) void prep_x_kernel(const float* __restrict__ x) {
    const int base = blockIdx.x * 1024 + threadIdx.x;   // word index, +i*256
    float4 v[8];
#pragma unroll
    for (int i = 0; i < 4; i++) {
        const float4* s = reinterpret_cast<const float4*>(x) + (base + i * 256) * 2;
        v[2 * i]     = s[0];
        v[2 * i + 1] = s[1];
    }
#pragma unroll
    for (int i = 0; i < 4; i++) {
        const int w = base + i * 256;
        const float* f0 = reinterpret_cast<const float*>(&v[2 * i]);      // k 0..3
        const float* f1 = reinterpret_cast<const float*>(&v[2 * i + 1]);  // k 4..7
        __half2 h[4];
        h[0] = __floats2half2_rn(f0[0], f1[0]);
        h[1] = __floats2half2_rn(f0[1], f1[1]);
        h[2] = __floats2half2_rn(f0[2], f1[2]);
        h[3] = __floats2half2_rn(f0[3], f1[3]);
        *reinterpret_cast<uint4*>(g_xh + w * 8) = *reinterpret_cast<const uint4*>(h);
    }
}

// ---------------------------------------------------------------------------
// Kernel 2: fused int4-dequant GEMM via mma.sync m16n8k16 (fp16 in, fp32 acc)
// CTA: 64m x 64n x K/8, 4 warps (2m x 2n), warp tile 32m x 32n.
// Grid (172, 8): blockIdx.x = n-tile, blockIdx.y = k-split.
// SMEM swizzle: 16B group kg at row r lives at  r*128 + ((kg ^ (r&7))*16).
// ---------------------------------------------------------------------------
__device__ __forceinline__ void dequant_word(unsigned word, uint32_t zz, uint32_t s2,
                                             uint32_t sts) {
    uint32_t r[4];
#pragma unroll
    for (int j = 0; j < 4; j++) {
        uint32_t p;
        asm("lop3.b32 %0, %1, 0x000F000F, 0x64006400, 0xEA;" : "=r"(p) : "r"(word >> (4 * j)));
        asm("sub.rn.f16x2 %0, %0, %1;" : "+r"(p) : "r"(zz));
        asm("mul.rn.f16x2 %0, %1, %2;" : "=r"(r[j]) : "r"(p), "r"(s2));
    }
    asm volatile("st.shared.v4.b32 [%0], {%1,%2,%3,%4};"
        :: "r"(sts), "r"(r[0]), "r"(r[1]), "r"(r[2]), "r"(r[3]) : "memory");
}

__global__ __launch_bounds__(NTHREADS, 5)
void gptq_hmma_kernel(const int*   __restrict__ qweight,  // [K/8, N]
                      const int*   __restrict__ qzeros,   // [NGROUPS, N/8]
                      const float* __restrict__ scales)   // [NGROUPS, N]
{
    __shared__ __half a_s[2][M_DIM * KC];   // x tile   2 x 8 KB
    __shared__ __half w_s[2][NTILE * KC];   // W tile   2 x 8 KB

    const int tid   = threadIdx.x;
    const int lane  = tid & 31;
    const int wid   = tid >> 5;
    const int nblk  = blockIdx.x * NTILE;
    const int split = blockIdx.y;
    const int cbase = split * CPS;

    const uint32_t a_base = smem_u32(a_s);
    const uint32_t w_base = smem_u32(w_s);

    // ---- dequant assignment: 4 qweight words / thread / chunk (one column)
    const int dq_n  = tid & 63;             // local n
    const int kwh   = tid >> 6;             // 0/1 -> words 0-3 or 4-7
    const int dq_gn = nblk + dq_n;
    uint32_t dq_sts[4];
#pragma unroll
    for (int j = 0; j < 4; j++)
        dq_sts[j] = w_base + (uint32_t)(dq_n * 128 + (((kwh * 4 + j) ^ (dq_n & 7)) * 16));

    // ---- x stage assignment: four 16B groups / thread / chunk
    uint32_t xs_dst[4];
    const __half* xs_src[4];
#pragma unroll
    for (int i = 0; i < 4; i++) {
        const int v  = tid + i * NTHREADS;   // 0..511
        const int m  = v >> 3;
        const int kg = v & 7;
        xs_dst[i] = a_base + (uint32_t)(m * 128 + ((kg ^ (m & 7)) * 16));
        xs_src[i] = g_xh + m * K_DIM + cbase * KC + kg * 8;
    }

    // ---- compute assignment: warp (wm, wn), tile 32m x 32n
    const int wm = wid & 1, wn = wid >> 1;
    const int m0  = wm * 32;
    const int nw0 = wn * 32;
    const int lrow_a = m0  + (lane & 15);
    const int lrow_b = nw0 + (lane & 15);
    const int khalf  = lane >> 4;            // 0: k+0, 1: k+8
    const uint32_t ldm_a0 = a_base + (uint32_t)(lrow_a * 128);
    const uint32_t ldm_a1 = ldm_a0 + 16u * 128u;     // rows +16 (same swizzle phase)
    const uint32_t ldm_b0 = w_base + (uint32_t)(lrow_b * 128);
    const uint32_t ldm_b1 = ldm_b0 + 16u * 128u;
    const int swz_a = lrow_a & 7, swz_b = lrow_b & 7;

    float acc[2][2][2][4] = {};   // [mi][nj][n8][4]

    // ================= stage chunk 0 of this split =================
    {
#pragma unroll
        for (int i = 0; i < 4; i++)
            asm volatile("cp.async.ca.shared.global [%0], [%1], 16;"
                :: "r"(xs_dst[i]), "l"(xs_src[i]) : "memory");
        asm volatile("cp.async.commit_group;" ::: "memory");

        const int c0 = cbase;
        const int g  = c0 >> 1;
        unsigned w[4];
#pragma unroll
        for (int j = 0; j < 4; j++)
            w[j] = (unsigned)qweight[(c0 * 8 + kwh * 4 + j) * N_DIM + dq_gn];
        const float    s  = scales[g * N_DIM + dq_gn];
        const int      zw = qzeros[g * (N_DIM / 8) + (dq_gn >> 3)];
        const int      z  = ((zw >> ((dq_gn & 7) * 4)) & 15) + 1;
        const uint32_t zz = 0x64006400u + (uint32_t)z * 0x00010001u;
        const uint16_t hb = __half_as_ushort(__float2half_rn(s));
        const uint32_t s2 = ((uint32_t)hb << 16) | hb;
#pragma unroll
        for (int j = 0; j < 4; j++) dequant_word(w[j], zz, s2, dq_sts[j]);
        asm volatile("cp.async.wait_group 0;" ::: "memory");
    }
    __syncthreads();

    // ================= main loop =================
#pragma unroll 1
    for (int lc = 0; lc < CPS; lc++) {
        const uint32_t aoff  = (uint32_t)((lc & 1) * (M_DIM * KC * 2));
        const uint32_t woff  = (uint32_t)((lc & 1) * (NTILE * KC * 2));
        const uint32_t naoff = (uint32_t)(((lc + 1) & 1) * (M_DIM * KC * 2));
        const uint32_t nwoff = (uint32_t)(((lc + 1) & 1) * (NTILE * KC * 2));

        unsigned nwd[4]; uint32_t nzz = 0, ns2 = 0;
        const bool has_next = (lc + 1 < CPS);
        if (has_next) {
            const int nc = cbase + lc + 1;
#pragma unroll
            for (int i = 0; i < 4; i++)
                asm volatile("cp.async.ca.shared.global [%0], [%1], 16;"
                    :: "r"(xs_dst[i] + naoff), "l"(xs_src[i] + (lc + 1) * KC) : "memory");
            asm volatile("cp.async.commit_group;" ::: "memory");

            const int g = nc >> 1;
#pragma unroll
            for (int j = 0; j < 4; j++)
                nwd[j] = (unsigned)qweight[(nc * 8 + kwh * 4 + j) * N_DIM + dq_gn];
            const float s  = scales[g * N_DIM + dq_gn];
            const int   zw = qzeros[g * (N_DIM / 8) + (dq_gn >> 3)];
            const int   z  = ((zw >> ((dq_gn & 7) * 4)) & 15) + 1;
            nzz = 0x64006400u + (uint32_t)z * 0x00010001u;
            const uint16_t hb = __half_as_ushort(__float2half_rn(s));
            ns2 = ((uint32_t)hb << 16) | hb;
        }

        // ---- compute chunk: 4 k-tiles of 16; per kt: 4 LDSM, 8 MMA
#pragma unroll
        for (int kt = 0; kt < 4; kt++) {
            const int kg = 2 * kt + khalf;
            uint32_t a0[4], a1[4], b0[4], b1[4];
            asm volatile("ldmatrix.sync.aligned.m8n8.x4.shared.b16 {%0,%1,%2,%3}, [%4];"
                : "=r"(a0[0]), "=r"(a0[1]), "=r"(a0[2]), "=r"(a0[3])
                : "r"(ldm_a0 + aoff + (uint32_t)((kg ^ swz_a) * 16)));
            asm volatile("ldmatrix.sync.aligned.m8n8.x4.shared.b16 {%0,%1,%2,%3}, [%4];"
                : "=r"(a1[0]), "=r"(a1[1]), "=r"(a1[2]), "=r"(a1[3])
                : "r"(ldm_a1 + aoff + (uint32_t)((kg ^ swz_a) * 16)));
            asm volatile("ldmatrix.sync.aligned.m8n8.x4.shared.b16 {%0,%1,%2,%3}, [%4];"
                : "=r"(b0[0]), "=r"(b0[1]), "=r"(b0[2]), "=r"(b0[3])
                : "r"(ldm_b0 + woff + (uint32_t)((kg ^ swz_b) * 16)));
            asm volatile("ldmatrix.sync.aligned.m8n8.x4.shared.b16 {%0,%1,%2,%3}, [%4];"
                : "=r"(b1[0]), "=r"(b1[1]), "=r"(b1[2]), "=r"(b1[3])
                : "r"(ldm_b1 + woff + (uint32_t)((kg ^ swz_b) * 16)));
#pragma unroll
            for (int mi = 0; mi < 2; mi++) {
                const uint32_t* a = mi ? a1 : a0;
#pragma unroll
                for (int nj = 0; nj < 2; nj++) {
                    const uint32_t* b = nj ? b1 : b0;
                    asm volatile(
                        "mma.sync.aligned.m16n8k16.row.col.f32.f16.f16.f32 "
                        "{%0,%1,%2,%3}, {%4,%5,%6,%7}, {%8,%9}, {%0,%1,%2,%3};"
                        : "+f"(acc[mi][nj][0][0]), "+f"(acc[mi][nj][0][1]),
                          "+f"(acc[mi][nj][0][2]), "+f"(acc[mi][nj][0][3])
                        : "r"(a[0]), "r"(a[1]), "r"(a[2]), "r"(a[3]), "r"(b[0]), "r"(b[2]));
                    asm volatile(
                        "mma.sync.aligned.m16n8k16.row.col.f32.f16.f16.f32 "
                        "{%0,%1,%2,%3}, {%4,%5,%6,%7}, {%8,%9}, {%0,%1,%2,%3};"
                        : "+f"(acc[mi][nj][1][0]), "+f"(acc[mi][nj][1][1]),
                          "+f"(acc[mi][nj][1][2]), "+f"(acc[mi][nj][1][3])
                        : "r"(a[0]), "r"(a[1]), "r"(a[2]), "r"(a[3]), "r"(b[1]), "r"(b[3]));
                }
            }
        }

        if (has_next) {
            dequant_word(nwd[0], nzz, ns2, dq_sts[0] + nwoff);
            dequant_word(nwd[1], nzz, ns2, dq_sts[1] + nwoff);
            dequant_word(nwd[2], nzz, ns2, dq_sts[2] + nwoff);
            dequant_word(nwd[3], nzz, ns2, dq_sts[3] + nwoff);
            asm volatile("cp.async.wait_group 0;" ::: "memory");
        }
        __syncthreads();
    }

    // ====== epilogue: flat coalesced partial dump (16KB contiguous / CTA) ======
    // float4 index j*128 + tid,  j = mi*4 + nj*2 + t. Reduce kernel owns the map.
    {
        float4* part = g_part4 + ((size_t)split * NTB + blockIdx.x) * 1024;
#pragma unroll
        for (int mi = 0; mi < 2; mi++)
#pragma unroll
            for (int nj = 0; nj < 2; nj++)
#pragma unroll
                for (int t = 0; t < 2; t++) {
                    const int j = mi * 4 + nj * 2 + t;
                    part[j * 128 + tid] = make_float4(acc[mi][nj][t][0], acc[mi][nj][t][1],
                                                      acc[mi][nj][t][2], acc[mi][nj][t][3]);
                }
    }
}

// ---------------------------------------------------------------------------
// Kernel 3: reduce partials + bias -> out.  One CTA per n-tile (64n x 64m).
// Inverse of the gemm fragment map:
//   m = wm*32 + mi*16 + (lane>>2) + (e>>1)*8
//   n = wn*32 + nj*16 + t*8 + (lane&3)*2 + (e&1)
// ---------------------------------------------------------------------------
__global__ __launch_bounds__(256) void reduce_kernel(const float* __restrict__ bias,
                                                     float* __restrict__ out) {
    __shared__ float4 sm[1024];
    const int r = blockIdx.x;
    const int t = threadIdx.x;
    const float4* base = g_part4 + (size_t)r * 1024;

#pragma unroll
    for (int ii = 0; ii < 4; ii++) {
        const int idx = ii * 256 + t;
        float4 s = base[idx];
#pragma unroll
        for (int p = 1; p < SPLIT; p++) {
            const float4 v = base[(size_t)p * (NTB * 1024) + idx];
            s.x += v.x; s.y += v.y; s.z += v.z; s.w += v.w;
        }
        sm[idx] = s;
    }
    __syncthreads();

    const float* smf = reinterpret_cast<const float*>(sm);
#pragma unroll
    for (int iter = 0; iter < 16; iter++) {
        const int m = iter * 4 + (t >> 6);
        const int c = t & 63;
        const int lane = ((m & 7) << 2) | ((c >> 1) & 3);
        const int wd   = ((m >> 5) & 1) | (((c >> 5) & 1) << 1);
        const int j    = (((m >> 4) & 1) << 2) | (((c >> 4) & 1) << 1) | ((c >> 3) & 1);
        const int e    = (((m >> 3) & 1) << 1) | (c & 1);
        const float v  = smf[(((j * 128) + (wd * 32 + lane)) << 2) | e];
        const int n    = r * NTILE + c;
        out[(size_t)m * N_DIM + n] = v + bias[n];
    }
}

// ---------------------------------------------------------------------------
extern "C" void kernel_launch(void* const* d_in, const int* in_sizes, int n_in,
                              void* d_out, int out_size) {
    const float* x       = (const float*)d_in[0];
    const int*   qweight = (const int*)  d_in[1];
    const int*   qzeros  = (const int*)  d_in[2];
    const float* scales  = (const float*)d_in[3];
    const float* bias    = (const float*)d_in[4];
    float*       out     = (float*)d_out;

    prep_x_kernel<<<32, 256>>>(x);
    gptq_hmma_kernel<<<dim3(NTB, SPLIT), NTHREADS>>>(qweight, qzeros, scales);
    reduce_kernel<<<NTB, 256>>>(bias, out);
}